// round 2
// baseline (speedup 1.0000x reference)
#include <cuda_runtime.h>

// Problem constants (fixed by the dataset)
#define NN 20000      // nodes
#define EE 640000     // edges
#define BBATCH 2      // batch
#define HH 128        // hidden (= IN)
#define OO 10         // out dim

// ---------------- scratch (static device globals; no runtime alloc) ----------
__device__ int   g_deg[NN];
__device__ int   g_fill[NN];
__device__ int   g_rowptr[NN + 1];
__device__ int   g_csr[EE];
__device__ float g_dinv[NN];
__device__ int   g_is64;
// node-major interleaved: row r = n*2+b, 128 floats per row
__device__ __align__(16) float g_buf0[BBATCH * NN * HH];
__device__ __align__(16) float g_buf1[BBATCH * NN * HH];
__device__ float g_bnsum[HH];
__device__ float g_bnsq[HH];
__device__ float g_scale[HH];
__device__ float g_shift[HH];

// ---------------- edge dtype probe ------------------------------------------
// int64 little-endian with values < 2^31 has zero high words at odd int32
// positions; random int32 node ids in [0,20000) essentially never do.
__global__ void k_detect(const int* __restrict__ ei32) {
    if (threadIdx.x == 0 && blockIdx.x == 0) {
        int all0 = 1;
        for (int i = 0; i < 64; i++)
            if (ei32[2 * i + 1] != 0) { all0 = 0; break; }
        g_is64 = all0;
    }
}

__device__ __forceinline__ int edge_at(const void* eiv, long idx) {
    return g_is64 ? (int)((const long long*)eiv)[idx]
                  : ((const int*)eiv)[idx];
}

// ---------------- graph prep ------------------------------------------------
__global__ void k_zero() {
    int i = blockIdx.x * blockDim.x + threadIdx.x;
    if (i < NN) { g_deg[i] = 0; g_fill[i] = 0; }
}

__global__ void k_count(const void* __restrict__ eiv) {
    int e = blockIdx.x * blockDim.x + threadIdx.x;
    if (e < EE) atomicAdd(&g_deg[edge_at(eiv, (long)EE + e)], 1);
}

// exclusive scan of g_deg into g_rowptr, single block of 1024 threads
__global__ void k_scan() {
    __shared__ int ssum[1024];
    const int CH = 20;                 // 1024*20 = 20480 >= NN+1
    int t = threadIdx.x;
    int base = t * CH;
    int loc[CH];
    int s = 0;
#pragma unroll
    for (int i = 0; i < CH; i++) {
        int idx = base + i;
        int c = (idx < NN) ? g_deg[idx] : 0;
        loc[i] = s;
        s += c;
    }
    ssum[t] = s;
    __syncthreads();
    for (int off = 1; off < 1024; off <<= 1) {
        int add = (t >= off) ? ssum[t - off] : 0;
        __syncthreads();
        ssum[t] += add;
        __syncthreads();
    }
    int pre = ssum[t] - s;             // exclusive prefix of this thread's chunk
#pragma unroll
    for (int i = 0; i < CH; i++) {
        int idx = base + i;
        if (idx <= NN) g_rowptr[idx] = pre + loc[i];
    }
}

__global__ void k_fill(const void* __restrict__ eiv) {
    int e = blockIdx.x * blockDim.x + threadIdx.x;
    if (e < EE) {
        int d = edge_at(eiv, (long)EE + e);
        int p = g_rowptr[d] + atomicAdd(&g_fill[d], 1);
        g_csr[p] = edge_at(eiv, e);
    }
}

__global__ void k_dinv() {
    int i = blockIdx.x * blockDim.x + threadIdx.x;
    if (i < NN) g_dinv[i] = rsqrtf((float)(g_deg[i] + 1));   // +1 = self loop
}

// ---------------- GEMM: C[n*2+b] = affine(A_row) @ W ------------------------
// ALAYOUT 0: A row = b*NN + n (batch-major external x)
// ALAYOUT 1: A row = n*2 + b (node-interleaved internal buffer), A==nullptr -> g_buf1
// C always g_buf0, node-interleaved.
template <int ALAYOUT, bool AFFINE>
__global__ void __launch_bounds__(256) k_gemm(const float* __restrict__ Ain,
                                              const float* __restrict__ W) {
    __shared__ __align__(16) float As[8][128];
    __shared__ __align__(16) float Ws[8][128];
    const float* A = (ALAYOUT == 0) ? Ain : (const float*)g_buf1;

    int tid = threadIdx.x;
    int b = blockIdx.y;
    int rowBase = blockIdx.x * 128;

    int ldRow = rowBase + (tid >> 1);
    int nClamp = ldRow < NN ? ldRow : NN - 1;
    long aIdx = (ALAYOUT == 0) ? ((long)b * NN + nClamp) * HH
                               : ((long)nClamp * BBATCH + b) * HH;
    int seg = tid & 1;

    int ty = tid >> 4, tx = tid & 15;
    float acc[8][8];
#pragma unroll
    for (int i = 0; i < 8; i++)
#pragma unroll
        for (int j = 0; j < 8; j++) acc[i][j] = 0.f;

    int wk = tid >> 5;
    int wc = (tid & 31) * 4;

    for (int kt = 0; kt < 16; ++kt) {
        int k0 = kt * 8 + seg * 4;
        float4 av = *(const float4*)(A + aIdx + k0);
        if (AFFINE) {
            av.x = av.x * g_scale[k0 + 0] + g_shift[k0 + 0];
            av.y = av.y * g_scale[k0 + 1] + g_shift[k0 + 1];
            av.z = av.z * g_scale[k0 + 2] + g_shift[k0 + 2];
            av.w = av.w * g_scale[k0 + 3] + g_shift[k0 + 3];
        }
        int r = tid >> 1;
        As[seg * 4 + 0][r] = av.x;
        As[seg * 4 + 1][r] = av.y;
        As[seg * 4 + 2][r] = av.z;
        As[seg * 4 + 3][r] = av.w;

        float4 wv = *(const float4*)(W + (kt * 8 + wk) * HH + wc);
        *(float4*)&Ws[wk][wc] = wv;
        __syncthreads();

#pragma unroll
        for (int k = 0; k < 8; k++) {
            float a[8], w[8];
            *(float4*)(a)     = *(float4*)&As[k][ty * 8];
            *(float4*)(a + 4) = *(float4*)&As[k][ty * 8 + 4];
            *(float4*)(w)     = *(float4*)&Ws[k][tx * 8];
            *(float4*)(w + 4) = *(float4*)&Ws[k][tx * 8 + 4];
#pragma unroll
            for (int i = 0; i < 8; i++)
#pragma unroll
                for (int j = 0; j < 8; j++) acc[i][j] += a[i] * w[j];
        }
        __syncthreads();
    }

#pragma unroll
    for (int i = 0; i < 8; i++) {
        int n = rowBase + ty * 8 + i;
        if (n < NN) {
            float* Cp = g_buf0 + ((long)n * BBATCH + b) * HH + tx * 8;
            *(float4*)(Cp)     = make_float4(acc[i][0], acc[i][1], acc[i][2], acc[i][3]);
            *(float4*)(Cp + 4) = make_float4(acc[i][4], acc[i][5], acc[i][6], acc[i][7]);
        }
    }
}

// ---------------- aggregation: buf0 -> buf1, relu(agg + bias) ---------------
// one warp per node, both batches (node row = 1KB, lanes read float4s)
__global__ void __launch_bounds__(256) k_agg(const float* __restrict__ bias) {
    int warp = (blockIdx.x * blockDim.x + threadIdx.x) >> 5;
    int lane = threadIdx.x & 31;
    if (warp >= NN) return;
    int node = warp;
    float din = g_dinv[node];

    const float4* h4 = (const float4*)g_buf0;
    long base = (long)node * 64;          // 64 float4 per node row (2 batches)
    float4 v0 = h4[base + lane];
    float4 v1 = h4[base + 32 + lane];
    float4 a0, a1;                         // self-loop: dinv[n]*h[n] (outer dinv later)
    a0.x = din * v0.x; a0.y = din * v0.y; a0.z = din * v0.z; a0.w = din * v0.w;
    a1.x = din * v1.x; a1.y = din * v1.y; a1.z = din * v1.z; a1.w = din * v1.w;

    int e = g_rowptr[node], end = g_rowptr[node + 1];
#pragma unroll 4
    for (; e < end; ++e) {
        int s = g_csr[e];
        float w = g_dinv[s];
        long sb = (long)s * 64;
        float4 u0 = h4[sb + lane];
        float4 u1 = h4[sb + 32 + lane];
        a0.x += w * u0.x; a0.y += w * u0.y; a0.z += w * u0.z; a0.w += w * u0.w;
        a1.x += w * u1.x; a1.y += w * u1.y; a1.z += w * u1.z; a1.w += w * u1.w;
    }

    float4 bv = *(const float4*)(bias + lane * 4);
    float4 r0, r1;
    r0.x = fmaxf(din * a0.x + bv.x, 0.f);
    r0.y = fmaxf(din * a0.y + bv.y, 0.f);
    r0.z = fmaxf(din * a0.z + bv.z, 0.f);
    r0.w = fmaxf(din * a0.w + bv.w, 0.f);
    r1.x = fmaxf(din * a1.x + bv.x, 0.f);
    r1.y = fmaxf(din * a1.y + bv.y, 0.f);
    r1.z = fmaxf(din * a1.z + bv.z, 0.f);
    r1.w = fmaxf(din * a1.w + bv.w, 0.f);

    float4* o4 = (float4*)g_buf1;
    o4[base + lane] = r0;
    o4[base + 32 + lane] = r1;
}

// ---------------- batchnorm stats over buf1 ---------------------------------
__global__ void k_bnstats() {
    int c = threadIdx.x;                   // blockDim = 128
    float s = 0.f, q = 0.f;
    for (int r = blockIdx.x; r < BBATCH * NN; r += gridDim.x) {
        float v = g_buf1[(long)r * HH + c];
        s += v;
        q += v * v;
    }
    atomicAdd(&g_bnsum[c], s);
    atomicAdd(&g_bnsq[c], q);
}

__global__ void k_affine(const float* __restrict__ gamma,
                         const float* __restrict__ beta) {
    int c = threadIdx.x;                   // 128 threads
    float cnt = (float)(BBATCH * NN);
    float mean = g_bnsum[c] / cnt;
    float var = g_bnsq[c] / cnt - mean * mean;
    float inv = rsqrtf(var + 1e-5f);
    float sc = gamma[c] * inv;
    g_scale[c] = sc;
    g_shift[c] = beta[c] - mean * sc;
    g_bnsum[c] = 0.f;                      // ready for next use / next launch
    g_bnsq[c] = 0.f;
}

// ---------------- classifier: affine(buf1) @ Wc + bc -> out -----------------
__global__ void __launch_bounds__(256) k_cls(const float* __restrict__ Wc,
                                             const float* __restrict__ bc,
                                             float* __restrict__ out) {
    __shared__ float sW[HH * OO];
    __shared__ float sb[OO];
    for (int i = threadIdx.x; i < HH * OO; i += blockDim.x) sW[i] = Wc[i];
    if (threadIdx.x < OO) sb[threadIdx.x] = bc[threadIdx.x];
    __syncthreads();

    int warp = threadIdx.x >> 5;
    int lane = threadIdx.x & 31;
    int row = blockIdx.x * 8 + warp;       // row = n*2+b
    if (row >= BBATCH * NN) return;

    int k = lane * 4;
    float4 v = *(const float4*)(g_buf1 + (long)row * HH + k);
    v.x = v.x * g_scale[k + 0] + g_shift[k + 0];
    v.y = v.y * g_scale[k + 1] + g_shift[k + 1];
    v.z = v.z * g_scale[k + 2] + g_shift[k + 2];
    v.w = v.w * g_scale[k + 3] + g_shift[k + 3];

    float p[OO];
#pragma unroll
    for (int c = 0; c < OO; c++) {
        p[c] = v.x * sW[(k + 0) * OO + c] + v.y * sW[(k + 1) * OO + c] +
               v.z * sW[(k + 2) * OO + c] + v.w * sW[(k + 3) * OO + c];
    }
#pragma unroll
    for (int c = 0; c < OO; c++) {
#pragma unroll
        for (int o = 16; o > 0; o >>= 1)
            p[c] += __shfl_xor_sync(0xffffffffu, p[c], o);
    }
    if (lane < OO) {
        int n = row >> 1, b = row & 1;
        out[((long)b * NN + n) * OO + lane] = p[lane] + sb[lane];
    }
}

// ---------------- launch ----------------------------------------------------
extern "C" void kernel_launch(void* const* d_in, const int* in_sizes, int n_in,
                              void* d_out, int out_size) {
    const float* x  = (const float*)d_in[0];
    const float* W1 = (const float*)d_in[1];
    const float* b1 = (const float*)d_in[2];
    const float* W2 = (const float*)d_in[3];
    const float* b2 = (const float*)d_in[4];
    const float* g1 = (const float*)d_in[5];
    const float* bt1 = (const float*)d_in[6];
    const float* g2 = (const float*)d_in[7];
    const float* bt2 = (const float*)d_in[8];
    const float* Wc = (const float*)d_in[9];
    const float* bc = (const float*)d_in[10];
    const void* ei = d_in[11];
    float* out = (float*)d_out;

    // graph prep
    k_detect<<<1, 32>>>((const int*)ei);
    k_zero<<<(NN + 255) / 256, 256>>>();
    k_count<<<(EE + 255) / 256, 256>>>(ei);
    k_scan<<<1, 1024>>>();
    k_fill<<<(EE + 255) / 256, 256>>>(ei);
    k_dinv<<<(NN + 255) / 256, 256>>>();

    dim3 ggrid((NN + 127) / 128, BBATCH);

    // layer 1
    k_gemm<0, false><<<ggrid, 256>>>(x, W1);
    k_agg<<<(NN + 7) / 8, 256>>>(b1);
    k_bnstats<<<256, 128>>>();
    k_affine<<<1, 128>>>(g1, bt1);

    // layer 2 (BN affine fused into A-load)
    k_gemm<1, true><<<ggrid, 256>>>(nullptr, W2);
    k_agg<<<(NN + 7) / 8, 256>>>(b2);
    k_bnstats<<<256, 128>>>();
    k_affine<<<1, 128>>>(g2, bt2);

    // classifier (BN affine fused)
    k_cls<<<(BBATCH * NN + 7) / 8, 256>>>(Wc, bc, out);
}

// round 5
// speedup vs baseline: 1.1635x; 1.1635x over previous
#include <cuda_runtime.h>
#include <cstdint>

#define NN 20000
#define EE 640000
#define BBATCH 2
#define HH 128
#define OO 10

// ---------------- scratch ----------------------------------------------------
__device__ int   g_deg[NN];
__device__ int   g_fill[NN];
__device__ int   g_rowptr[NN + 1];
__device__ int2  g_csrw[EE];          // (src, dinv[src] bits)
__device__ float g_dinv[NN];
__device__ int   g_is64;
__device__ __align__(16) float g_buf0[BBATCH * NN * HH];
__device__ __align__(16) float g_buf1[BBATCH * NN * HH];
__device__ float g_bnsum[HH];
__device__ float g_bnsq[HH];
__device__ float g_scale[HH];
__device__ float g_shift[HH];
__device__ float g_rv[HH];
// W fragment packs (tf32 hi/lo): 16 k-chunks x 1024 floats (16 nt x 32 lanes x 2 regs)
__device__ __align__(16) float g_fW1hi[16384];
__device__ __align__(16) float g_fW1lo[16384];
__device__ __align__(16) float g_fW2hi[16384];
__device__ __align__(16) float g_fW2lo[16384];

// ---------------- helpers ----------------------------------------------------
__device__ __forceinline__ unsigned f2tf(float x) {
    unsigned r;
    asm("cvt.rna.tf32.f32 %0, %1;" : "=r"(r) : "f"(x));
    return r;
}

// B fragment (m16n8k8 tf32, PTX spec): lane=(n&7)*4+(k&3), reg=(k&7)>>2
// b0 = B[t][g], b1 = B[t+4][g]  with g=lane>>2, t=lane&3
__device__ __forceinline__ int fragIdx(int k, int n) {
    int kt = k >> 3, kk = k & 7;
    int t = kk & 3, r = kk >> 2;
    int nt = n >> 3, g = n & 7;
    int lane = (g << 2) | t;
    return ((kt * 16 + nt) * 32 + lane) * 2 + r;   // chunk stride 1024
}

__device__ __forceinline__ void mma_tf32(float* d, unsigned a0, unsigned a1,
                                         unsigned a2, unsigned a3,
                                         unsigned b0, unsigned b1) {
    asm volatile(
        "mma.sync.aligned.m16n8k8.row.col.f32.tf32.tf32.f32 "
        "{%0,%1,%2,%3},{%4,%5,%6,%7},{%8,%9},{%0,%1,%2,%3};\n"
        : "+f"(d[0]), "+f"(d[1]), "+f"(d[2]), "+f"(d[3])
        : "r"(a0), "r"(a1), "r"(a2), "r"(a3), "r"(b0), "r"(b1));
}

__device__ __forceinline__ int edge_at(const void* eiv, long idx) {
    return g_is64 ? (int)((const long long*)eiv)[idx] : ((const int*)eiv)[idx];
}

// ---------------- graph prep -------------------------------------------------
__global__ void k_zero(const int* __restrict__ ei32) {
    int i = blockIdx.x * blockDim.x + threadIdx.x;
    if (i < NN) { g_deg[i] = 0; g_fill[i] = 0; }
    if (i == 0) {
        int all0 = 1;
        for (int j = 0; j < 64; j++)
            if (ei32[2 * j + 1] != 0) { all0 = 0; break; }
        g_is64 = all0;
    }
}

__global__ void k_count(const void* __restrict__ eiv) {
    int e = blockIdx.x * blockDim.x + threadIdx.x;
    if (e < EE) atomicAdd(&g_deg[edge_at(eiv, (long)EE + e)], 1);
}

// warp-shuffle scan of g_deg -> g_rowptr (+dinv), 1024 threads
__global__ void k_scan() {
    const int CH = 20;
    __shared__ int wsum[32];
    int t = threadIdx.x, lane = t & 31, wid = t >> 5;
    int base = t * CH;
    int loc[CH];
    int s = 0;
#pragma unroll
    for (int i = 0; i < CH; i++) {
        int idx = base + i;
        int c = (idx < NN) ? g_deg[idx] : 0;
        loc[i] = s;
        s += c;
    }
    int v = s;
#pragma unroll
    for (int o = 1; o < 32; o <<= 1) {
        int u = __shfl_up_sync(0xffffffffu, v, o);
        if (lane >= o) v += u;
    }
    if (lane == 31) wsum[wid] = v;
    __syncthreads();
    if (wid == 0) {
        int w = wsum[lane];
#pragma unroll
        for (int o = 1; o < 32; o <<= 1) {
            int u = __shfl_up_sync(0xffffffffu, w, o);
            if (lane >= o) w += u;
        }
        wsum[lane] = w;
    }
    __syncthreads();
    int pre = v - s + (wid > 0 ? wsum[wid - 1] : 0);
#pragma unroll
    for (int i = 0; i < CH; i++) {
        int idx = base + i;
        if (idx <= NN) g_rowptr[idx] = pre + loc[i];
        if (idx < NN) {
            int deg = (i + 1 < CH) ? loc[i + 1] - loc[i] : s - loc[i];
            g_dinv[idx] = rsqrtf((float)(deg + 1));
        }
    }
}

__global__ void k_fillw(const void* __restrict__ eiv) {
    int e = blockIdx.x * blockDim.x + threadIdx.x;
    if (e < EE) {
        int d = edge_at(eiv, (long)EE + e);
        int p = g_rowptr[d] + atomicAdd(&g_fill[d], 1);
        int s = edge_at(eiv, e);
        g_csrw[p] = make_int2(s, __float_as_int(g_dinv[s]));
    }
}

// ---------------- W1 fragment pack -------------------------------------------
__global__ void k_prepw1(const float* __restrict__ W) {
    int n = threadIdx.x;
    int k0 = blockIdx.x * 8;
    for (int k = k0; k < k0 + 8; k++) {
        float w = W[k * HH + n];
        unsigned hi = f2tf(w);
        unsigned lo = f2tf(w - __uint_as_float(hi));
        int idx = fragIdx(k, n);
        g_fW1hi[idx] = __uint_as_float(hi);
        g_fW1lo[idx] = __uint_as_float(lo);
    }
}

// ---------------- tensor-core GEMM: C = A @ Wfrag (+rv) ----------------------
// ALAYOUT 0: A row = b*NN+n (external x); 1: row = n*2+b (g_buf1)
// WSEL 0: W1 frags; 1: W2 frags. Output g_buf0 node-interleaved.
template <int ALAYOUT, int WSEL, bool RV>
__global__ void __launch_bounds__(256) k_gemm_tc(const float* __restrict__ Ain) {
    __shared__ __align__(16) float sHi[2][1024];
    __shared__ __align__(16) float sLo[2][1024];
    const float* A = ALAYOUT ? (const float*)g_buf1 : Ain;
    const float* fH = WSEL ? g_fW2hi : g_fW1hi;
    const float* fL = WSEL ? g_fW2lo : g_fW1lo;

    int tid = threadIdx.x, lane = tid & 31, warp = tid >> 5;
    int b = blockIdx.y;
    int rowBase = blockIdx.x * 128;
    int g = lane >> 2, t = lane & 3;
    int r0 = rowBase + warp * 16 + g;
    int r1 = r0 + 8;
    int rc0 = r0 < NN ? r0 : NN - 1;
    int rc1 = r1 < NN ? r1 : NN - 1;
    long a0b = ALAYOUT ? ((long)rc0 * 2 + b) * HH : ((long)b * NN + rc0) * HH;
    long a1b = ALAYOUT ? ((long)rc1 * 2 + b) * HH : ((long)b * NN + rc1) * HH;

    float acc[16][4];
#pragma unroll
    for (int i = 0; i < 16; i++)
#pragma unroll
        for (int j = 0; j < 4; j++) acc[i][j] = 0.f;

    int ld = tid * 4;                    // 256 threads x 4 = 1024 floats per buf
    *(float4*)&sHi[0][ld] = *(const float4*)&fH[ld];
    *(float4*)&sLo[0][ld] = *(const float4*)&fL[ld];
    __syncthreads();

    for (int c = 0; c < 16; c++) {
        int cur = c & 1;
        float4 nh, nl;
        if (c < 15) {
            nh = *(const float4*)&fH[(c + 1) * 1024 + ld];
            nl = *(const float4*)&fL[(c + 1) * 1024 + ld];
        }
        int k0 = c * 8;
        // A frag (PTX spec): a0=(r0,t) a1=(r1,t) a2=(r0,t+4) a3=(r1,t+4)
        float fa0 = A[a0b + k0 + t];
        float fa1 = A[a1b + k0 + t];
        float fa2 = A[a0b + k0 + t + 4];
        float fa3 = A[a1b + k0 + t + 4];
        unsigned ah0 = f2tf(fa0), ah1 = f2tf(fa1), ah2 = f2tf(fa2), ah3 = f2tf(fa3);
        unsigned al0 = f2tf(fa0 - __uint_as_float(ah0));
        unsigned al1 = f2tf(fa1 - __uint_as_float(ah1));
        unsigned al2 = f2tf(fa2 - __uint_as_float(ah2));
        unsigned al3 = f2tf(fa3 - __uint_as_float(ah3));

#pragma unroll
        for (int nt = 0; nt < 16; nt++) {
            float2 bh = *(const float2*)&sHi[cur][nt * 64 + lane * 2];
            float2 bl = *(const float2*)&sLo[cur][nt * 64 + lane * 2];
            unsigned bh0 = __float_as_uint(bh.x), bh1 = __float_as_uint(bh.y);
            unsigned bl0 = __float_as_uint(bl.x), bl1 = __float_as_uint(bl.y);
            mma_tf32(acc[nt], ah0, ah1, ah2, ah3, bh0, bh1);
            mma_tf32(acc[nt], al0, al1, al2, al3, bh0, bh1);
            mma_tf32(acc[nt], ah0, ah1, ah2, ah3, bl0, bl1);
        }
        __syncthreads();
        if (c < 15) {
            int nxt = cur ^ 1;
            *(float4*)&sHi[nxt][ld] = nh;
            *(float4*)&sLo[nxt][ld] = nl;
        }
        __syncthreads();
    }

#pragma unroll
    for (int nt = 0; nt < 16; nt++) {
        int col = nt * 8 + 2 * t;
        float o0 = acc[nt][0], o1 = acc[nt][1], o2 = acc[nt][2], o3 = acc[nt][3];
        if (RV) {
            float2 rv = *(const float2*)&g_rv[col];
            o0 += rv.x; o1 += rv.y; o2 += rv.x; o3 += rv.y;
        }
        if (r0 < NN)
            *(float2*)&g_buf0[((long)r0 * 2 + b) * HH + col] = make_float2(o0, o1);
        if (r1 < NN)
            *(float2*)&g_buf0[((long)r1 * 2 + b) * HH + col] = make_float2(o2, o3);
    }
}

// ---------------- aggregation + fused BN stats -------------------------------
__global__ void __launch_bounds__(256) k_aggbn(const float* __restrict__ bias) {
    __shared__ float ssum[HH], ssq[HH];
    int tid = threadIdx.x;
    if (tid < HH) { ssum[tid] = 0.f; ssq[tid] = 0.f; }
    __syncthreads();

    int node = (blockIdx.x * blockDim.x + tid) >> 5;   // grid*8 == NN exactly
    int lane = tid & 31;
    float din = g_dinv[node];

    const float4* h4 = (const float4*)g_buf0;
    long base = (long)node * 64;
    float4 v0 = h4[base + lane];
    float4 v1 = h4[base + 32 + lane];
    float4 a0, a1;
    a0.x = din * v0.x; a0.y = din * v0.y; a0.z = din * v0.z; a0.w = din * v0.w;
    a1.x = din * v1.x; a1.y = din * v1.y; a1.z = din * v1.z; a1.w = din * v1.w;

    int e = g_rowptr[node], end = g_rowptr[node + 1];
#pragma unroll 4
    for (; e < end; ++e) {
        int2 sw = g_csrw[e];
        int s = sw.x;
        float w = __int_as_float(sw.y);
        long sb = (long)s * 64;
        float4 u0 = h4[sb + lane];
        float4 u1 = h4[sb + 32 + lane];
        a0.x += w * u0.x; a0.y += w * u0.y; a0.z += w * u0.z; a0.w += w * u0.w;
        a1.x += w * u1.x; a1.y += w * u1.y; a1.z += w * u1.z; a1.w += w * u1.w;
    }

    float4 bv = *(const float4*)(bias + lane * 4);
    float4 rr0, rr1;
    rr0.x = fmaxf(din * a0.x + bv.x, 0.f);
    rr0.y = fmaxf(din * a0.y + bv.y, 0.f);
    rr0.z = fmaxf(din * a0.z + bv.z, 0.f);
    rr0.w = fmaxf(din * a0.w + bv.w, 0.f);
    rr1.x = fmaxf(din * a1.x + bv.x, 0.f);
    rr1.y = fmaxf(din * a1.y + bv.y, 0.f);
    rr1.z = fmaxf(din * a1.z + bv.z, 0.f);
    rr1.w = fmaxf(din * a1.w + bv.w, 0.f);

    float4* o4 = (float4*)g_buf1;
    o4[base + lane] = rr0;
    o4[base + 32 + lane] = rr1;

    int ch = lane * 4;
    atomicAdd(&ssum[ch + 0], rr0.x + rr1.x);
    atomicAdd(&ssum[ch + 1], rr0.y + rr1.y);
    atomicAdd(&ssum[ch + 2], rr0.z + rr1.z);
    atomicAdd(&ssum[ch + 3], rr0.w + rr1.w);
    atomicAdd(&ssq[ch + 0], rr0.x * rr0.x + rr1.x * rr1.x);
    atomicAdd(&ssq[ch + 1], rr0.y * rr0.y + rr1.y * rr1.y);
    atomicAdd(&ssq[ch + 2], rr0.z * rr0.z + rr1.z * rr1.z);
    atomicAdd(&ssq[ch + 3], rr0.w * rr0.w + rr1.w * rr1.w);
    __syncthreads();
    if (tid < HH) {
        atomicAdd(&g_bnsum[tid], ssum[tid]);
        atomicAdd(&g_bnsq[tid], ssq[tid]);
    }
}

// ---------------- BN affine (+optional fold into W2 frags + rv) --------------
template <bool PACK>
__global__ void k_affine_t(const float* __restrict__ gamma,
                           const float* __restrict__ beta,
                           const float* __restrict__ W2) {
    __shared__ float sscale[HH], sshift[HH];
    int c = threadIdx.x;
    float cnt = (float)(BBATCH * NN);
    float mean = g_bnsum[c] / cnt;
    float var = g_bnsq[c] / cnt - mean * mean;
    float inv = rsqrtf(var + 1e-5f);
    float sc = gamma[c] * inv;
    float sh = beta[c] - mean * sc;
    g_scale[c] = sc;
    g_shift[c] = sh;
    sscale[c] = sc;
    sshift[c] = sh;
    g_bnsum[c] = 0.f;
    g_bnsq[c] = 0.f;
    if (PACK) {
        __syncthreads();
        float rv = 0.f;
        for (int k = 0; k < HH; k++) {
            float w = W2[k * HH + c];
            float wp = sscale[k] * w;
            rv += sshift[k] * w;
            unsigned hi = f2tf(wp);
            unsigned lo = f2tf(wp - __uint_as_float(hi));
            int idx = fragIdx(k, c);
            g_fW2hi[idx] = __uint_as_float(hi);
            g_fW2lo[idx] = __uint_as_float(lo);
        }
        g_rv[c] = rv;
    }
}

// ---------------- classifier -------------------------------------------------
__global__ void __launch_bounds__(256) k_cls(const float* __restrict__ Wc,
                                             const float* __restrict__ bc,
                                             float* __restrict__ out) {
    __shared__ float sW[HH * OO];
    __shared__ float sb[OO];
    for (int i = threadIdx.x; i < HH * OO; i += blockDim.x) sW[i] = Wc[i];
    if (threadIdx.x < OO) sb[threadIdx.x] = bc[threadIdx.x];
    __syncthreads();

    int warp = threadIdx.x >> 5;
    int lane = threadIdx.x & 31;
    int row = blockIdx.x * 8 + warp;
    if (row >= BBATCH * NN) return;

    int k = lane * 4;
    float4 v = *(const float4*)(g_buf1 + (long)row * HH + k);
    v.x = v.x * g_scale[k + 0] + g_shift[k + 0];
    v.y = v.y * g_scale[k + 1] + g_shift[k + 1];
    v.z = v.z * g_scale[k + 2] + g_shift[k + 2];
    v.w = v.w * g_scale[k + 3] + g_shift[k + 3];

    float p[OO];
#pragma unroll
    for (int c = 0; c < OO; c++) {
        p[c] = v.x * sW[(k + 0) * OO + c] + v.y * sW[(k + 1) * OO + c] +
               v.z * sW[(k + 2) * OO + c] + v.w * sW[(k + 3) * OO + c];
    }
#pragma unroll
    for (int c = 0; c < OO; c++) {
#pragma unroll
        for (int o = 16; o > 0; o >>= 1)
            p[c] += __shfl_xor_sync(0xffffffffu, p[c], o);
    }
    if (lane < OO) {
        int n = row >> 1, b = row & 1;
        out[((long)b * NN + n) * OO + lane] = p[lane] + sb[lane];
    }
}

// ---------------- launch -----------------------------------------------------
extern "C" void kernel_launch(void* const* d_in, const int* in_sizes, int n_in,
                              void* d_out, int out_size) {
    const float* x  = (const float*)d_in[0];
    const float* W1 = (const float*)d_in[1];
    const float* b1 = (const float*)d_in[2];
    const float* W2 = (const float*)d_in[3];
    const float* b2 = (const float*)d_in[4];
    const float* g1 = (const float*)d_in[5];
    const float* bt1 = (const float*)d_in[6];
    const float* g2 = (const float*)d_in[7];
    const float* bt2 = (const float*)d_in[8];
    const float* Wc = (const float*)d_in[9];
    const float* bc = (const float*)d_in[10];
    const void* ei = d_in[11];
    float* out = (float*)d_out;

    k_zero<<<(NN + 255) / 256, 256>>>((const int*)ei);
    k_count<<<(EE + 255) / 256, 256>>>(ei);
    k_scan<<<1, 1024>>>();
    k_fillw<<<(EE + 255) / 256, 256>>>(ei);
    k_prepw1<<<16, 128>>>(W1);

    dim3 ggrid((NN + 127) / 128, BBATCH);

    // layer 1
    k_gemm_tc<0, 0, false><<<ggrid, 256>>>(x);
    k_aggbn<<<NN / 8, 256>>>(b1);
    k_affine_t<true><<<1, 128>>>(g1, bt1, W2);   // BN affine folded into W2' + rv

    // layer 2
    k_gemm_tc<1, 1, true><<<ggrid, 256>>>(nullptr);
    k_aggbn<<<NN / 8, 256>>>(b2);
    k_affine_t<false><<<1, 128>>>(g2, bt2, nullptr);

    // classifier (BN2 affine fused)
    k_cls<<<(BBATCH * NN + 7) / 8, 256>>>(Wc, bc, out);
}

// round 6
// speedup vs baseline: 1.3571x; 1.1664x over previous
#include <cuda_runtime.h>
#include <cstdint>

#define NN 20000
#define EE 640000
#define BBATCH 2
#define HH 128
#define OO 10
#define PAD 192

// ---------------- scratch ----------------------------------------------------
__device__ int   g_fill[NN];          // degree counter / final degree
__device__ int   g_ell[NN * PAD];     // ELL adjacency (src ids)
__device__ float g_dinv[NN];
__device__ int   g_is64;
__device__ __align__(16) float g_buf0[BBATCH * NN * HH];
__device__ __align__(16) float g_buf1[BBATCH * NN * HH];
__device__ float g_bnsum[HH];
__device__ float g_bnsq[HH];
__device__ float g_scale[HH];
__device__ float g_shift[HH];
__device__ float g_rv[HH];
// W fragment packs (tf32 hi/lo): 16 k-chunks x 1024 floats (16 nt x 32 lanes x 2 regs)
__device__ __align__(16) float g_fW1hi[16384];
__device__ __align__(16) float g_fW1lo[16384];
__device__ __align__(16) float g_fW2hi[16384];
__device__ __align__(16) float g_fW2lo[16384];

// ---------------- helpers ----------------------------------------------------
__device__ __forceinline__ unsigned f2tf(float x) {
    unsigned r;
    asm("cvt.rna.tf32.f32 %0, %1;" : "=r"(r) : "f"(x));
    return r;
}

// B fragment (m16n8k8 tf32, PTX spec): lane=(n&7)*4+(k&3), reg=(k&7)>>2
__device__ __forceinline__ int fragIdx(int k, int n) {
    int kt = k >> 3, kk = k & 7;
    int t = kk & 3, r = kk >> 2;
    int nt = n >> 3, g = n & 7;
    int lane = (g << 2) | t;
    return ((kt * 16 + nt) * 32 + lane) * 2 + r;   // chunk stride 1024
}

__device__ __forceinline__ void mma_tf32(float* d, unsigned a0, unsigned a1,
                                         unsigned a2, unsigned a3,
                                         unsigned b0, unsigned b1) {
    asm volatile(
        "mma.sync.aligned.m16n8k8.row.col.f32.tf32.tf32.f32 "
        "{%0,%1,%2,%3},{%4,%5,%6,%7},{%8,%9},{%0,%1,%2,%3};\n"
        : "+f"(d[0]), "+f"(d[1]), "+f"(d[2]), "+f"(d[3])
        : "r"(a0), "r"(a1), "r"(a2), "r"(a3), "r"(b0), "r"(b1));
}

__device__ __forceinline__ int edge_at2(const void* eiv, int is64, long idx) {
    return is64 ? (int)((const long long*)eiv)[idx] : ((const int*)eiv)[idx];
}

// ---------------- graph prep -------------------------------------------------
__global__ void k_zero(const int* __restrict__ ei32) {
    int i = blockIdx.x * blockDim.x + threadIdx.x;
    if (i < NN) g_fill[i] = 0;
    if (blockIdx.x == 0 && threadIdx.x < 32) {
        int lane = threadIdx.x;
        int nz = (ei32[2 * lane + 1] != 0) | (ei32[2 * (lane + 32) + 1] != 0);
        unsigned m = __ballot_sync(0xffffffffu, nz);
        if (lane == 0) g_is64 = (m == 0);
    }
}

__global__ void k_fill_ell(const void* __restrict__ eiv) {
    int is64 = g_is64;
    long e0 = (long)(blockIdx.x * blockDim.x + threadIdx.x) * 4;   // grid covers EE exactly
    int s[4], d[4];
#pragma unroll
    for (int i = 0; i < 4; i++) {
        s[i] = edge_at2(eiv, is64, e0 + i);
        d[i] = edge_at2(eiv, is64, (long)EE + e0 + i);
    }
#pragma unroll
    for (int i = 0; i < 4; i++) {
        int p = atomicAdd(&g_fill[d[i]], 1);
        g_ell[d[i] * PAD + p] = s[i];
    }
}

__global__ void k_dinv() {
    int i = blockIdx.x * blockDim.x + threadIdx.x;
    if (i < NN) g_dinv[i] = rsqrtf((float)(g_fill[i] + 1));   // +1 = self loop
}

// ---------------- W1 fragment pack -------------------------------------------
__global__ void k_prepw1(const float* __restrict__ W) {
    int n = threadIdx.x;
    int k0 = blockIdx.x * 8;
    for (int k = k0; k < k0 + 8; k++) {
        float w = W[k * HH + n];
        unsigned hi = f2tf(w);
        unsigned lo = f2tf(w - __uint_as_float(hi));
        int idx = fragIdx(k, n);
        g_fW1hi[idx] = __uint_as_float(hi);
        g_fW1lo[idx] = __uint_as_float(lo);
    }
}

// ---------------- tensor-core GEMM: C = A @ Wfrag (+rv) ----------------------
template <int ALAYOUT, int WSEL, bool RV>
__global__ void __launch_bounds__(256) k_gemm_tc(const float* __restrict__ Ain) {
    __shared__ __align__(16) float sHi[2][1024];
    __shared__ __align__(16) float sLo[2][1024];
    const float* A = ALAYOUT ? (const float*)g_buf1 : Ain;
    const float* fH = WSEL ? g_fW2hi : g_fW1hi;
    const float* fL = WSEL ? g_fW2lo : g_fW1lo;

    int tid = threadIdx.x, lane = tid & 31, warp = tid >> 5;
    int b = blockIdx.y;
    int rowBase = blockIdx.x * 128;
    int g = lane >> 2, t = lane & 3;
    int r0 = rowBase + warp * 16 + g;
    int r1 = r0 + 8;
    int rc0 = r0 < NN ? r0 : NN - 1;
    int rc1 = r1 < NN ? r1 : NN - 1;
    long a0b = ALAYOUT ? ((long)rc0 * 2 + b) * HH : ((long)b * NN + rc0) * HH;
    long a1b = ALAYOUT ? ((long)rc1 * 2 + b) * HH : ((long)b * NN + rc1) * HH;

    float acc[16][4];
#pragma unroll
    for (int i = 0; i < 16; i++)
#pragma unroll
        for (int j = 0; j < 4; j++) acc[i][j] = 0.f;

    int ld = tid * 4;
    *(float4*)&sHi[0][ld] = *(const float4*)&fH[ld];
    *(float4*)&sLo[0][ld] = *(const float4*)&fL[ld];
    __syncthreads();

    for (int c = 0; c < 16; c++) {
        int cur = c & 1;
        float4 nh, nl;
        if (c < 15) {
            nh = *(const float4*)&fH[(c + 1) * 1024 + ld];
            nl = *(const float4*)&fL[(c + 1) * 1024 + ld];
        }
        int k0 = c * 8;
        // A frag (PTX spec): a0=(r0,t) a1=(r1,t) a2=(r0,t+4) a3=(r1,t+4)
        float fa0 = A[a0b + k0 + t];
        float fa1 = A[a1b + k0 + t];
        float fa2 = A[a0b + k0 + t + 4];
        float fa3 = A[a1b + k0 + t + 4];
        unsigned ah0 = f2tf(fa0), ah1 = f2tf(fa1), ah2 = f2tf(fa2), ah3 = f2tf(fa3);
        unsigned al0 = f2tf(fa0 - __uint_as_float(ah0));
        unsigned al1 = f2tf(fa1 - __uint_as_float(ah1));
        unsigned al2 = f2tf(fa2 - __uint_as_float(ah2));
        unsigned al3 = f2tf(fa3 - __uint_as_float(ah3));

#pragma unroll
        for (int nt = 0; nt < 16; nt++) {
            float2 bh = *(const float2*)&sHi[cur][nt * 64 + lane * 2];
            float2 bl = *(const float2*)&sLo[cur][nt * 64 + lane * 2];
            unsigned bh0 = __float_as_uint(bh.x), bh1 = __float_as_uint(bh.y);
            unsigned bl0 = __float_as_uint(bl.x), bl1 = __float_as_uint(bl.y);
            mma_tf32(acc[nt], ah0, ah1, ah2, ah3, bh0, bh1);
            mma_tf32(acc[nt], al0, al1, al2, al3, bh0, bh1);
            mma_tf32(acc[nt], ah0, ah1, ah2, ah3, bl0, bl1);
        }
        __syncthreads();
        if (c < 15) {
            int nxt = cur ^ 1;
            *(float4*)&sHi[nxt][ld] = nh;
            *(float4*)&sLo[nxt][ld] = nl;
        }
        __syncthreads();
    }

#pragma unroll
    for (int nt = 0; nt < 16; nt++) {
        int col = nt * 8 + 2 * t;
        float o0 = acc[nt][0], o1 = acc[nt][1], o2 = acc[nt][2], o3 = acc[nt][3];
        if (RV) {
            float2 rv = *(const float2*)&g_rv[col];
            o0 += rv.x; o1 += rv.y; o2 += rv.x; o3 += rv.y;
        }
        if (r0 < NN)
            *(float2*)&g_buf0[((long)r0 * 2 + b) * HH + col] = make_float2(o0, o1);
        if (r1 < NN)
            *(float2*)&g_buf0[((long)r1 * 2 + b) * HH + col] = make_float2(o2, o3);
    }
}

// ---------------- aggregation + fused BN stats -------------------------------
__global__ void __launch_bounds__(256) k_aggbn(const float* __restrict__ bias) {
    __shared__ float ssum[HH], ssq[HH];
    int tid = threadIdx.x;
    if (tid < HH) { ssum[tid] = 0.f; ssq[tid] = 0.f; }
    __syncthreads();

    int node = (blockIdx.x * blockDim.x + tid) >> 5;   // grid*8 == NN exactly
    int lane = tid & 31;
    float din = g_dinv[node];

    const float4* h4 = (const float4*)g_buf0;
    long base = (long)node * 64;
    float4 v0 = h4[base + lane];
    float4 v1 = h4[base + 32 + lane];
    float4 a0, a1;
    a0.x = din * v0.x; a0.y = din * v0.y; a0.z = din * v0.z; a0.w = din * v0.w;
    a1.x = din * v1.x; a1.y = din * v1.y; a1.z = din * v1.z; a1.w = din * v1.w;

    int cnt = g_fill[node];
    const int* row = g_ell + node * PAD;
#pragma unroll 4
    for (int i = 0; i < cnt; ++i) {
        int s = row[i];
        float w = g_dinv[s];
        long sb = (long)s * 64;
        float4 u0 = h4[sb + lane];
        float4 u1 = h4[sb + 32 + lane];
        a0.x += w * u0.x; a0.y += w * u0.y; a0.z += w * u0.z; a0.w += w * u0.w;
        a1.x += w * u1.x; a1.y += w * u1.y; a1.z += w * u1.z; a1.w += w * u1.w;
    }

    float4 bv = *(const float4*)(bias + lane * 4);
    float4 rr0, rr1;
    rr0.x = fmaxf(din * a0.x + bv.x, 0.f);
    rr0.y = fmaxf(din * a0.y + bv.y, 0.f);
    rr0.z = fmaxf(din * a0.z + bv.z, 0.f);
    rr0.w = fmaxf(din * a0.w + bv.w, 0.f);
    rr1.x = fmaxf(din * a1.x + bv.x, 0.f);
    rr1.y = fmaxf(din * a1.y + bv.y, 0.f);
    rr1.z = fmaxf(din * a1.z + bv.z, 0.f);
    rr1.w = fmaxf(din * a1.w + bv.w, 0.f);

    float4* o4 = (float4*)g_buf1;
    o4[base + lane] = rr0;
    o4[base + 32 + lane] = rr1;

    int ch = lane * 4;
    atomicAdd(&ssum[ch + 0], rr0.x + rr1.x);
    atomicAdd(&ssum[ch + 1], rr0.y + rr1.y);
    atomicAdd(&ssum[ch + 2], rr0.z + rr1.z);
    atomicAdd(&ssum[ch + 3], rr0.w + rr1.w);
    atomicAdd(&ssq[ch + 0], rr0.x * rr0.x + rr1.x * rr1.x);
    atomicAdd(&ssq[ch + 1], rr0.y * rr0.y + rr1.y * rr1.y);
    atomicAdd(&ssq[ch + 2], rr0.z * rr0.z + rr1.z * rr1.z);
    atomicAdd(&ssq[ch + 3], rr0.w * rr0.w + rr1.w * rr1.w);
    __syncthreads();
    if (tid < HH) {
        atomicAdd(&g_bnsum[tid], ssum[tid]);
        atomicAdd(&g_bnsq[tid], ssq[tid]);
    }
}

// ---------------- BN affine (+optional fold into W2 frags + rv) --------------
template <bool PACK>
__global__ void k_affine_t(const float* __restrict__ gamma,
                           const float* __restrict__ beta,
                           const float* __restrict__ W2) {
    __shared__ float sscale[HH], sshift[HH];
    int c = threadIdx.x;
    float cnt = (float)(BBATCH * NN);
    float mean = g_bnsum[c] / cnt;
    float var = g_bnsq[c] / cnt - mean * mean;
    float inv = rsqrtf(var + 1e-5f);
    float sc = gamma[c] * inv;
    float sh = beta[c] - mean * sc;
    g_scale[c] = sc;
    g_shift[c] = sh;
    sscale[c] = sc;
    sshift[c] = sh;
    g_bnsum[c] = 0.f;
    g_bnsq[c] = 0.f;
    if (PACK) {
        __syncthreads();
        float rv = 0.f;
        for (int k = 0; k < HH; k++) {
            float w = W2[k * HH + c];
            float wp = sscale[k] * w;
            rv += sshift[k] * w;
            unsigned hi = f2tf(wp);
            unsigned lo = f2tf(wp - __uint_as_float(hi));
            int idx = fragIdx(k, c);
            g_fW2hi[idx] = __uint_as_float(hi);
            g_fW2lo[idx] = __uint_as_float(lo);
        }
        g_rv[c] = rv;
    }
}

// ---------------- classifier -------------------------------------------------
__global__ void __launch_bounds__(256) k_cls(const float* __restrict__ Wc,
                                             const float* __restrict__ bc,
                                             float* __restrict__ out) {
    __shared__ float sW[HH * OO];
    __shared__ float sb[OO];
    for (int i = threadIdx.x; i < HH * OO; i += blockDim.x) sW[i] = Wc[i];
    if (threadIdx.x < OO) sb[threadIdx.x] = bc[threadIdx.x];
    __syncthreads();

    int warp = threadIdx.x >> 5;
    int lane = threadIdx.x & 31;
    int row = blockIdx.x * 8 + warp;
    if (row >= BBATCH * NN) return;

    int k = lane * 4;
    float4 v = *(const float4*)(g_buf1 + (long)row * HH + k);
    v.x = v.x * g_scale[k + 0] + g_shift[k + 0];
    v.y = v.y * g_scale[k + 1] + g_shift[k + 1];
    v.z = v.z * g_scale[k + 2] + g_shift[k + 2];
    v.w = v.w * g_scale[k + 3] + g_shift[k + 3];

    float p[OO];
#pragma unroll
    for (int c = 0; c < OO; c++) {
        p[c] = v.x * sW[(k + 0) * OO + c] + v.y * sW[(k + 1) * OO + c] +
               v.z * sW[(k + 2) * OO + c] + v.w * sW[(k + 3) * OO + c];
    }
#pragma unroll
    for (int c = 0; c < OO; c++) {
#pragma unroll
        for (int o = 16; o > 0; o >>= 1)
            p[c] += __shfl_xor_sync(0xffffffffu, p[c], o);
    }
    if (lane < OO) {
        int n = row >> 1, b = row & 1;
        out[((long)b * NN + n) * OO + lane] = p[lane] + sb[lane];
    }
}

// ---------------- launch -----------------------------------------------------
extern "C" void kernel_launch(void* const* d_in, const int* in_sizes, int n_in,
                              void* d_out, int out_size) {
    const float* x  = (const float*)d_in[0];
    const float* W1 = (const float*)d_in[1];
    const float* b1 = (const float*)d_in[2];
    const float* W2 = (const float*)d_in[3];
    const float* b2 = (const float*)d_in[4];
    const float* g1 = (const float*)d_in[5];
    const float* bt1 = (const float*)d_in[6];
    const float* g2 = (const float*)d_in[7];
    const float* bt2 = (const float*)d_in[8];
    const float* Wc = (const float*)d_in[9];
    const float* bc = (const float*)d_in[10];
    const void* ei = d_in[11];
    float* out = (float*)d_out;

    dim3 ggrid((NN + 127) / 128, BBATCH);

    // Fork: W1 pack + layer-1 GEMM (depends only on x, W1) runs concurrently
    // with the graph build on the main stream.
    cudaStream_t s1;
    cudaStreamCreateWithFlags(&s1, cudaStreamNonBlocking);
    cudaEvent_t ev0, ev1;
    cudaEventCreateWithFlags(&ev0, cudaEventDisableTiming);
    cudaEventCreateWithFlags(&ev1, cudaEventDisableTiming);

    cudaEventRecord(ev0, 0);
    cudaStreamWaitEvent(s1, ev0, 0);
    k_prepw1<<<16, 128, 0, s1>>>(W1);
    k_gemm_tc<0, 0, false><<<ggrid, 256, 0, s1>>>(x);
    cudaEventRecord(ev1, s1);

    // main stream: graph build
    k_zero<<<(NN + 255) / 256, 256>>>((const int*)ei);
    k_fill_ell<<<EE / 1024, 256>>>(ei);
    k_dinv<<<(NN + 255) / 256, 256>>>();

    // join
    cudaStreamWaitEvent(0, ev1, 0);

    // layer 1 tail
    k_aggbn<<<NN / 8, 256>>>(b1);
    k_affine_t<true><<<1, 128>>>(g1, bt1, W2);   // BN affine folded into W2' + rv

    // layer 2
    k_gemm_tc<1, 1, true><<<ggrid, 256>>>(nullptr);
    k_aggbn<<<NN / 8, 256>>>(b2);
    k_affine_t<false><<<1, 128>>>(g2, bt2, nullptr);

    // classifier (BN2 affine fused)
    k_cls<<<(BBATCH * NN + 7) / 8, 256>>>(Wc, bc, out);
}